// round 1
// baseline (speedup 1.0000x reference)
#include <cuda_runtime.h>
#include <math.h>

// ============================================================================
// BlobRegressionLoss: mean(top-k BCE) + 0.5 * soft-dice-loss
//   n = 9,437,184 fp32 elements, k = int(0.2*n)
// Strategy: exact radix-select on fp32 bit patterns (all losses > 0, so
// uint32 bit order == float order). 12/12/8-bit three-level select, then one
// exact sum pass above the pivot with tie correction. Dice sums fused into
// the first pass with double accumulation.
// ============================================================================

#define MAX_N 9437184

__device__ unsigned int g_keys[MAX_N];
__device__ unsigned int g_hist0[4096];
__device__ unsigned int g_hist1[4096];
__device__ unsigned int g_hist2[256];
__device__ double g_sum_p;
__device__ double g_sum_pt;
__device__ double g_sum_t;
__device__ double g_topk_sum;
__device__ unsigned int g_prefix;
__device__ unsigned int g_krem;

// ---------------------------------------------------------------------------
__global__ void zero_all(unsigned int k) {
    int i = blockIdx.x * blockDim.x + threadIdx.x;
    if (i < 4096) { g_hist0[i] = 0u; g_hist1[i] = 0u; }
    if (i < 256)  { g_hist2[i] = 0u; }
    if (i == 0) {
        g_sum_p = 0.0; g_sum_pt = 0.0; g_sum_t = 0.0; g_topk_sum = 0.0;
        g_prefix = 0u; g_krem = k;
    }
}

// ---------------------------------------------------------------------------
__device__ __forceinline__ double block_reduce(double v, double* sh) {
    int lane = threadIdx.x & 31, wid = threadIdx.x >> 5;
    #pragma unroll
    for (int o = 16; o; o >>= 1) v += __shfl_down_sync(0xffffffffu, v, o);
    if (lane == 0) sh[wid] = v;
    __syncthreads();
    v = (threadIdx.x < (blockDim.x >> 5)) ? sh[threadIdx.x] : 0.0;
    if (wid == 0) {
        #pragma unroll
        for (int o = 16; o; o >>= 1) v += __shfl_down_sync(0xffffffffu, v, o);
    }
    return v;
}

// Compute BCE loss key + accumulate dice partial sums. One expf per element.
__device__ __forceinline__ unsigned int loss_key(float x, float t,
                                                 double& sp, double& spt, double& st) {
    float ax = fabsf(x);
    float e  = expf(-ax);                       // exp(-|x|)
    float loss = fmaxf(x, 0.0f) - x * t + log1pf(e);
    // sigmoid via the same exp: x>=0 -> 1/(1+e), x<0 -> e/(1+e)
    float inv = 1.0f / (1.0f + e);
    float p   = (x >= 0.0f) ? inv : (e * inv);
    sp  += (double)p;
    spt += (double)p * (double)t;
    st  += (double)t;
    return __float_as_uint(loss);
}

// Pass A: compute loss keys, 12-bit high histogram, dice sums.
__global__ void pass_a(const float4* __restrict__ x4, const float4* __restrict__ t4,
                       const float* __restrict__ x1, const float* __restrict__ t1,
                       int n4, int n) {
    __shared__ unsigned int sh[4096];
    __shared__ double shr[32];
    for (int i = threadIdx.x; i < 4096; i += blockDim.x) sh[i] = 0u;
    __syncthreads();

    double sp = 0.0, spt = 0.0, st = 0.0;
    int tid = blockIdx.x * blockDim.x + threadIdx.x;
    int stride = gridDim.x * blockDim.x;
    uint4* keys4 = reinterpret_cast<uint4*>(g_keys);

    for (int i = tid; i < n4; i += stride) {
        float4 xv = x4[i];
        float4 tv = t4[i];
        uint4 kk;
        kk.x = loss_key(xv.x, tv.x, sp, spt, st);
        kk.y = loss_key(xv.y, tv.y, sp, spt, st);
        kk.z = loss_key(xv.z, tv.z, sp, spt, st);
        kk.w = loss_key(xv.w, tv.w, sp, spt, st);
        keys4[i] = kk;
        atomicAdd(&sh[kk.x >> 20], 1u);
        atomicAdd(&sh[kk.y >> 20], 1u);
        atomicAdd(&sh[kk.z >> 20], 1u);
        atomicAdd(&sh[kk.w >> 20], 1u);
    }
    // scalar tail
    int base = n4 * 4;
    int rem = n - base;
    if (tid < rem) {
        unsigned int key = loss_key(x1[base + tid], t1[base + tid], sp, spt, st);
        g_keys[base + tid] = key;
        atomicAdd(&sh[key >> 20], 1u);
    }
    __syncthreads();

    for (int i = threadIdx.x; i < 4096; i += blockDim.x) {
        unsigned int v = sh[i];
        if (v) atomicAdd(&g_hist0[i], v);
    }

    double r = block_reduce(sp, shr);
    if (threadIdx.x == 0) atomicAdd(&g_sum_p, r);
    __syncthreads();
    r = block_reduce(spt, shr);
    if (threadIdx.x == 0) atomicAdd(&g_sum_pt, r);
    __syncthreads();
    r = block_reduce(st, shr);
    if (threadIdx.x == 0) atomicAdd(&g_sum_t, r);
}

// ---------------------------------------------------------------------------
// Single-block select: find bin b such that count(bins > b) < krem <= count(bins >= b).
// Updates g_prefix (shifted) and g_krem. LEVEL: 0 -> hist0 (12b), 1 -> hist1 (12b),
// 2 -> hist2 (8b). Launch <<<1, 1024>>>.
template <int LEVEL>
__global__ void select_k() {
    const unsigned int* hist = (LEVEL == 0) ? g_hist0 : ((LEVEL == 1) ? g_hist1 : g_hist2);
    constexpr int NBINS = (LEVEL == 2) ? 256 : 4096;
    constexpr int PER = (NBINS + 1023) / 1024;
    constexpr int BITS = (LEVEL == 2) ? 8 : 12;

    __shared__ unsigned int s[1024];
    __shared__ unsigned int s_krem;
    int t = threadIdx.x;
    if (t == 0) s_krem = g_krem;

    int lo = t * PER;
    int hi = (lo + PER < NBINS) ? (lo + PER) : NBINS;
    unsigned int h[PER > 0 ? PER : 1];
    unsigned int local = 0;
    #pragma unroll
    for (int j = 0; j < PER; j++) {
        unsigned int v = (lo + j < hi) ? hist[lo + j] : 0u;
        h[j] = v;
        local += v;
    }
    s[t] = local;
    __syncthreads();
    unsigned int krem = s_krem;

    // inclusive suffix scan: s[t] = sum of local[t..1023]
    for (int off = 1; off < 1024; off <<= 1) {
        unsigned int v = (t + off < 1024) ? s[t + off] : 0u;
        __syncthreads();
        s[t] += v;
        __syncthreads();
    }

    unsigned int run = s[t] - local;  // count strictly above my chunk
    for (int j = hi - 1; j >= lo; j--) {
        unsigned int c = h[j - lo];
        if (run < krem && run + c >= krem) {
            g_prefix = (g_prefix << BITS) | (unsigned int)j;
            g_krem = krem - run;
        }
        run += c;
    }
}

// ---------------------------------------------------------------------------
// Filtered histogram passes. LEVEL 1: match bits[31:20], hist bits[19:8].
// LEVEL 2: match bits[31:8], hist bits[7:0].
template <int LEVEL>
__global__ void pass_c(int n4, int n) {
    constexpr int NBINS = (LEVEL == 1) ? 4096 : 256;
    __shared__ unsigned int sh[NBINS];
    for (int i = threadIdx.x; i < NBINS; i += blockDim.x) sh[i] = 0u;
    __syncthreads();

    unsigned int prefix = g_prefix;
    int tid = blockIdx.x * blockDim.x + threadIdx.x;
    int stride = gridDim.x * blockDim.x;
    const uint4* keys4 = reinterpret_cast<const uint4*>(g_keys);

    for (int i = tid; i < n4; i += stride) {
        uint4 kk = keys4[i];
        unsigned int ks[4] = {kk.x, kk.y, kk.z, kk.w};
        #pragma unroll
        for (int j = 0; j < 4; j++) {
            unsigned int key = ks[j];
            if (LEVEL == 1) {
                if ((key >> 20) == prefix) atomicAdd(&sh[(key >> 8) & 0xFFFu], 1u);
            } else {
                if ((key >> 8) == prefix) atomicAdd(&sh[key & 0xFFu], 1u);
            }
        }
    }
    int base = n4 * 4;
    int rem = n - base;
    if (tid < rem) {
        unsigned int key = g_keys[base + tid];
        if (LEVEL == 1) {
            if ((key >> 20) == prefix) atomicAdd(&sh[(key >> 8) & 0xFFFu], 1u);
        } else {
            if ((key >> 8) == prefix) atomicAdd(&sh[key & 0xFFu], 1u);
        }
    }
    __syncthreads();

    unsigned int* ghist = (LEVEL == 1) ? g_hist1 : g_hist2;
    for (int i = threadIdx.x; i < NBINS; i += blockDim.x) {
        unsigned int v = sh[i];
        if (v) atomicAdd(&ghist[i], v);
    }
}

// ---------------------------------------------------------------------------
// Final pass: sum of all values with key strictly greater than pivot.
__global__ void pass_d(int n4, int n) {
    __shared__ double shr[32];
    unsigned int pivot = g_prefix;  // full 32-bit key after 3 select levels
    double s = 0.0;
    int tid = blockIdx.x * blockDim.x + threadIdx.x;
    int stride = gridDim.x * blockDim.x;
    const uint4* keys4 = reinterpret_cast<const uint4*>(g_keys);

    for (int i = tid; i < n4; i += stride) {
        uint4 kk = keys4[i];
        if (kk.x > pivot) s += (double)__uint_as_float(kk.x);
        if (kk.y > pivot) s += (double)__uint_as_float(kk.y);
        if (kk.z > pivot) s += (double)__uint_as_float(kk.z);
        if (kk.w > pivot) s += (double)__uint_as_float(kk.w);
    }
    int base = n4 * 4;
    int rem = n - base;
    if (tid < rem) {
        unsigned int key = g_keys[base + tid];
        if (key > pivot) s += (double)__uint_as_float(key);
    }

    double r = block_reduce(s, shr);
    if (threadIdx.x == 0) atomicAdd(&g_topk_sum, r);
}

// ---------------------------------------------------------------------------
__global__ void finalize(float* out, int k) {
    double pivot_val = (double)__uint_as_float(g_prefix);
    double ksum = g_topk_sum + (double)g_krem * pivot_val;  // tie correction
    double bce = ksum / (double)k;
    double dice = (2.0 * g_sum_pt + 1e-6) / (g_sum_p + g_sum_t + 1e-6);
    out[0] = (float)(bce + 0.5 * (1.0 - dice));
}

// ---------------------------------------------------------------------------
extern "C" void kernel_launch(void* const* d_in, const int* in_sizes, int n_in,
                              void* d_out, int out_size) {
    const float* logits  = (const float*)d_in[0];
    const float* targets = (const float*)d_in[1];
    float* out = (float*)d_out;
    int n = in_sizes[0];
    int k = (int)((double)n * 0.2);
    if (k < 1) k = 1;
    int n4 = n / 4;

    const int BLOCKS = 1024;
    const int THREADS = 256;

    zero_all<<<4, 1024>>>((unsigned int)k);
    pass_a<<<BLOCKS, THREADS>>>((const float4*)logits, (const float4*)targets,
                                logits, targets, n4, n);
    select_k<0><<<1, 1024>>>();
    pass_c<1><<<BLOCKS, THREADS>>>(n4, n);
    select_k<1><<<1, 1024>>>();
    pass_c<2><<<BLOCKS, THREADS>>>(n4, n);
    select_k<2><<<1, 1024>>>();
    pass_d<<<BLOCKS, THREADS>>>(n4, n);
    finalize<<<1, 1>>>(out, k);
}